// round 9
// baseline (speedup 1.0000x reference)
#include <cuda_runtime.h>
#include <math.h>

#define B_DIM 64
#define K_DIM 128
#define H_DIM 64
#define W_DIM 64
#define PLANE (H_DIM * W_DIM)          // 4096 floats = 1024 float4
#define N_PLANES (B_DIM * K_DIM)       // 8192
#define N_BOXES 256
#define ALPHA 1.0f
#define BETA 0.5f
#define NPART 32
#define PART_STRIDE 32                 // 128B between accumulator slots

#define THREADS 512
#define GRID_CLS 560                   // 352 CTAs x15 planes + 208 x14 = 8192
#define GRID_LOC 32                    // 32 CTAs x 8 boxes = 256
#define GRID (GRID_CLS + GRID_LOC)     // 592 = 148 SMs x 4 CTAs: one wave

// Zero-initialized device globals; finalizer CTA resets them each run.
__device__ float g_cls_parts[NPART * PART_STRIDE];
__device__ float g_loc_parts[NPART * PART_STRIDE];
__device__ unsigned int g_done_count;

__device__ __forceinline__ float softplus_f(float x) {
    float ax = fabsf(x);
    return log1pf(expf(-ax)) + fmaxf(x, 0.0f);
}

// Monotonic float <-> uint encoding so float-max == uint-max.
__device__ __forceinline__ unsigned int enc_f(float f) {
    unsigned int u = __float_as_uint(f);
    return u ^ ((unsigned int)(((int)u) >> 31) | 0x80000000u);
}
__device__ __forceinline__ float dec_f(unsigned int e) {
    unsigned int u = (e & 0x80000000u) ? (e ^ 0x80000000u) : ~e;
    return __uint_as_float(u);
}

__device__ __forceinline__ unsigned int atom_add_release_gpu(unsigned int* addr, unsigned int v) {
    unsigned int old;
    asm volatile("atom.release.gpu.global.add.u32 %0, [%1], %2;"
                 : "=r"(old) : "l"(addr), "r"(v) : "memory");
    return old;
}

__global__ void __launch_bounds__(THREADS, 4) fused_loss_kernel(
    const float* __restrict__ cams,
    const float* __restrict__ concepts_gt,
    const int* __restrict__ box_b,
    const int* __restrict__ box_c,
    const int* __restrict__ y0v,
    const int* __restrict__ y1v,
    const int* __restrict__ x0v,
    const int* __restrict__ x1v,
    float* __restrict__ out)
{
    int t = threadIdx.x;
    int wid = t >> 5, lid = t & 31;
    int bid = blockIdx.x;

    __shared__ unsigned int sEnc[16];
    __shared__ float sIn[8], sOut[8];

    if (bid < GRID_CLS) {
        // ================= cls CTA: 14-15 planes, barrier-free loop =========
        int cnt   = 14 + (bid < 352 ? 1 : 0);
        int start = bid * 14 + min(bid, 352);

        if (t < 16) sEnc[t] = 0u;      // below every real encoding
        __syncthreads();

        for (int i = 0; i < cnt; i++) {
            const float4* p = reinterpret_cast<const float4*>(
                cams + (size_t)(start + i) * PLANE);
            float4 a = p[t];
            float4 b = p[t + 512];
            float m = fmaxf(fmaxf(fmaxf(a.x, a.y), fmaxf(a.z, a.w)),
                            fmaxf(fmaxf(b.x, b.y), fmaxf(b.z, b.w)));
#pragma unroll
            for (int off = 16; off > 0; off >>= 1)
                m = fmaxf(m, __shfl_xor_sync(0xFFFFFFFFu, m, off));
            if (lid == 0) atomicMax(&sEnc[i], enc_f(m));
        }
        __syncthreads();

        if (wid == 0) {
            float bce = 0.0f;
            if (lid < cnt) {
                float bm = dec_f(sEnc[lid]);
                float y = concepts_gt[start + lid];
                bce = y * softplus_f(-bm) + (1.0f - y) * softplus_f(bm);
            }
#pragma unroll
            for (int off = 16; off > 0; off >>= 1)
                bce += __shfl_xor_sync(0xFFFFFFFFu, bce, off);
            if (lid == 0)
                atomicAdd(&g_cls_parts[(bid & (NPART - 1)) * PART_STRIDE], bce);
        }
    } else {
        // ================= loc CTA: 8 boxes, barrier-free loop ==============
        int base = (bid - GRID_CLS) * 8;

        if (t < 8) { sIn[t] = 0.0f; sOut[t] = 0.0f; }
        __syncthreads();

        for (int i = 0; i < 8; i++) {
            int box = base + i;
            int b = box_b[box];
            int c = box_c[box];
            int y0 = y0v[box], y1 = y1v[box], x0 = x0v[box], x1 = x1v[box];

            const float4* p = reinterpret_cast<const float4*>(
                cams + ((size_t)b * K_DIM + c) * PLANE);

            float inside = 0.0f, outside = 0.0f;
#pragma unroll
            for (int half = 0; half < 2; half++) {
                int u = t + half * 512;
                float4 v = p[u];
                int row = u >> 4;            // 16 float4 per row (W=64)
                int col0 = (u & 15) << 2;
                bool rin = (row >= y0) && (row < y1);
                float vals[4] = {v.x, v.y, v.z, v.w};
#pragma unroll
                for (int j = 0; j < 4; j++) {
                    int col = col0 + j;
                    float e = __expf(-vals[j]);
                    float s = __fdividef(1.0f, 1.0f + e);
                    bool in = rin && (col >= x0) && (col < x1);
                    float d = s - 1.0f;
                    if (in) inside += d * d;
                    else    outside += s * s;
                }
            }
#pragma unroll
            for (int off = 16; off > 0; off >>= 1) {
                inside  += __shfl_xor_sync(0xFFFFFFFFu, inside, off);
                outside += __shfl_xor_sync(0xFFFFFFFFu, outside, off);
            }
            if (lid == 0) {
                atomicAdd(&sIn[i], inside);
                atomicAdd(&sOut[i], outside);
            }
        }
        __syncthreads();

        if (wid == 0) {
            float loss = 0.0f;
            if (lid < 8) {
                int box = base + lid;
                float area = (float)((y1v[box] - y0v[box]) * (x1v[box] - x0v[box]));
                const float eps = 1e-6f;
                loss = sIn[lid] / (area + eps) + sOut[lid] / ((float)PLANE - area + eps);
            }
#pragma unroll
            for (int off = 16; off > 0; off >>= 1)
                loss += __shfl_xor_sync(0xFFFFFFFFu, loss, off);
            if (lid == 0)
                atomicAdd(&g_loc_parts[(bid & (NPART - 1)) * PART_STRIDE], loss);
        }
    }

    // ---------------- completion + finalize (t0 did its own global adds) ----
    if (t == 0) {
        unsigned int prev = atom_add_release_gpu(&g_done_count, 1u);
        if (prev == GRID - 1) {
            asm volatile("fence.acq_rel.gpu;" ::: "memory");
            float cls = 0.0f, loc = 0.0f;
#pragma unroll
            for (int i = 0; i < NPART; i++) {
                cls += g_cls_parts[i * PART_STRIDE];
                loc += g_loc_parts[i * PART_STRIDE];
                g_cls_parts[i * PART_STRIDE] = 0.0f;
                g_loc_parts[i * PART_STRIDE] = 0.0f;
            }
            out[0] = ALPHA * (cls / (float)N_PLANES) + BETA * (loc / (float)N_BOXES);
            g_done_count = 0u;   // reset for next graph replay
        }
    }
}

extern "C" void kernel_launch(void* const* d_in, const int* in_sizes, int n_in,
                              void* d_out, int out_size) {
    const float* cams        = (const float*)d_in[0];
    const float* concepts_gt = (const float*)d_in[1];
    const int*   box_b       = (const int*)d_in[2];
    const int*   box_c       = (const int*)d_in[3];
    const int*   y0          = (const int*)d_in[4];
    const int*   y1          = (const int*)d_in[5];
    const int*   x0          = (const int*)d_in[6];
    const int*   x1          = (const int*)d_in[7];
    float* out = (float*)d_out;

    fused_loss_kernel<<<GRID, THREADS>>>(cams, concepts_gt, box_b, box_c,
                                         y0, y1, x0, x1, out);
}

// round 10
// speedup vs baseline: 1.2221x; 1.2221x over previous
#include <cuda_runtime.h>
#include <math.h>

#define B_DIM 64
#define K_DIM 128
#define H_DIM 64
#define W_DIM 64
#define PLANE (H_DIM * W_DIM)          // 4096 floats
#define N_PLANES (B_DIM * K_DIM)       // 8192
#define N_BOXES 256
#define N_BLOCKS (N_PLANES + N_BOXES)  // 8448
#define ALPHA 1.0f
#define BETA 0.5f
#define NPART 32
#define PART_STRIDE 32                 // 128B between accumulator slots

// Zero-initialized device globals; finalize kernel resets them each run.
__device__ float g_cls_parts[NPART * PART_STRIDE];
__device__ float g_loc_parts[NPART * PART_STRIDE];

__device__ __forceinline__ float softplus_f(float x) {
    float ax = fabsf(x);
    return log1pf(expf(-ax)) + fmaxf(x, 0.0f);
}

// Kernel 1: loc blocks [0,256) then cls blocks [256,8448).
// Block epilogue = ONE fire-and-forget atomicAdd (no counter, no fence).
__global__ __launch_bounds__(256) void main_kernel(
    const float* __restrict__ cams,
    const float* __restrict__ concepts_gt,
    const int* __restrict__ box_b,
    const int* __restrict__ box_c,
    const int* __restrict__ y0v,
    const int* __restrict__ y1v,
    const int* __restrict__ x0v,
    const int* __restrict__ x1v)
{
    int t = threadIdx.x;
    int wid = t >> 5, lid = t & 31;
    __shared__ float s0[8], s1[8];

    if (blockIdx.x < N_BOXES) {
        // ---------------- loc block: one box ----------------
        int box = blockIdx.x;
        int b = box_b[box];
        int c = box_c[box];
        int y0 = y0v[box], y1 = y1v[box], x0 = x0v[box], x1 = x1v[box];

        const float4* p = reinterpret_cast<const float4*>(
            cams + ((size_t)b * K_DIM + c) * PLANE);

        float inside = 0.0f, outside = 0.0f;
#pragma unroll
        for (int i = 0; i < 4; i++) {
            int u = i * 256 + t;        // float4 index within plane [0,1024)
            float4 v = p[u];
            int row = u >> 4;           // 16 float4 per row (W=64)
            int col0 = (u & 15) << 2;
            float vals[4] = {v.x, v.y, v.z, v.w};
            bool rin = (row >= y0) && (row < y1);
#pragma unroll
            for (int j = 0; j < 4; j++) {
                int col = col0 + j;
                float e = __expf(-vals[j]);
                float s = __fdividef(1.0f, 1.0f + e);
                bool in = rin && (col >= x0) && (col < x1);
                float d = s - 1.0f;
                if (in) inside += d * d;
                else    outside += s * s;
            }
        }
#pragma unroll
        for (int off = 16; off > 0; off >>= 1) {
            inside  += __shfl_xor_sync(0xFFFFFFFFu, inside, off);
            outside += __shfl_xor_sync(0xFFFFFFFFu, outside, off);
        }
        if (lid == 0) { s0[wid] = inside; s1[wid] = outside; }
        __syncthreads();
        if (t == 0) {
            float ti = 0.0f, to = 0.0f;
#pragma unroll
            for (int w = 0; w < 8; w++) { ti += s0[w]; to += s1[w]; }
            float area = (float)((y1 - y0) * (x1 - x0));
            const float eps = 1e-6f;
            float loss = ti / (area + eps) + to / ((float)PLANE - area + eps);
            atomicAdd(&g_loc_parts[(box & (NPART - 1)) * PART_STRIDE], loss);
        }
    } else {
        // ---------------- cls block: one (b,k) plane ----------------
        int plane = blockIdx.x - N_BOXES;
        const float4* p = reinterpret_cast<const float4*>(cams + (size_t)plane * PLANE);

        float m = -INFINITY;
#pragma unroll
        for (int i = 0; i < 4; i++) {
            float4 v = p[i * 256 + t];
            m = fmaxf(m, fmaxf(fmaxf(v.x, v.y), fmaxf(v.z, v.w)));
        }
#pragma unroll
        for (int off = 16; off > 0; off >>= 1)
            m = fmaxf(m, __shfl_xor_sync(0xFFFFFFFFu, m, off));
        if (lid == 0) s0[wid] = m;
        __syncthreads();
        if (t == 0) {
            float bm = s0[0];
#pragma unroll
            for (int w = 1; w < 8; w++) bm = fmaxf(bm, s0[w]);
            float y = concepts_gt[plane];
            float bce = y * softplus_f(-bm) + (1.0f - y) * softplus_f(bm);
            atomicAdd(&g_cls_parts[(plane & (NPART - 1)) * PART_STRIDE], bce);
        }
    }
}

// Kernel 2: one warp sums the part slots, writes out, resets slots.
// Kernel boundary orders kernel-1 atomics before these reads.
__global__ void finalize_kernel(float* __restrict__ out) {
    int lid = threadIdx.x;   // 32 threads
    float cls = g_cls_parts[lid * PART_STRIDE];
    float loc = g_loc_parts[lid * PART_STRIDE];
    g_cls_parts[lid * PART_STRIDE] = 0.0f;
    g_loc_parts[lid * PART_STRIDE] = 0.0f;
#pragma unroll
    for (int off = 16; off > 0; off >>= 1) {
        cls += __shfl_xor_sync(0xFFFFFFFFu, cls, off);
        loc += __shfl_xor_sync(0xFFFFFFFFu, loc, off);
    }
    if (lid == 0)
        out[0] = ALPHA * (cls / (float)N_PLANES) + BETA * (loc / (float)N_BOXES);
}

extern "C" void kernel_launch(void* const* d_in, const int* in_sizes, int n_in,
                              void* d_out, int out_size) {
    const float* cams        = (const float*)d_in[0];
    const float* concepts_gt = (const float*)d_in[1];
    const int*   box_b       = (const int*)d_in[2];
    const int*   box_c       = (const int*)d_in[3];
    const int*   y0          = (const int*)d_in[4];
    const int*   y1          = (const int*)d_in[5];
    const int*   x0          = (const int*)d_in[6];
    const int*   x1          = (const int*)d_in[7];
    float* out = (float*)d_out;

    main_kernel<<<N_BLOCKS, 256>>>(cams, concepts_gt, box_b, box_c, y0, y1, x0, x1);
    finalize_kernel<<<1, 32>>>(out);
}